// round 16
// baseline (speedup 1.0000x reference)
#include <cuda_runtime.h>
#include <cuda_fp16.h>
#include <cstdint>
#include <math.h>

#define BB   128
#define TT   256
#define EE   384
#define HH   6
#define DHH  64
#define LL   6
#define VV   65
#define FFD  1536
#define BT   (BB*TT)          // 32768
#define E3   (3*EE)           // 1152
#define EPSV 1e-5f

// ======================= helpers =======================
__device__ __forceinline__ uint32_t smem_to_u32(const void* p) {
    uint32_t a;
    asm("{ .reg .u64 t; cvta.to.shared.u64 t, %1; cvt.u32.u64 %0, t; }" : "=r"(a) : "l"(p));
    return a;
}
__device__ __forceinline__ void cp_async16(uint32_t saddr, const void* gptr) {
    asm volatile("cp.async.cg.shared.global [%0], [%1], 16;" :: "r"(saddr), "l"(gptr));
}
#define CP_COMMIT() asm volatile("cp.async.commit_group;" ::: "memory")
#define CP_WAIT0()  asm volatile("cp.async.wait_group 0;" ::: "memory")
#define CP_WAIT1()  asm volatile("cp.async.wait_group 1;" ::: "memory")

// fp16 mma with fp32 accumulate
__device__ __forceinline__ void mma_f16(float* c, const uint32_t* a, const uint32_t* b) {
    asm volatile(
        "mma.sync.aligned.m16n8k16.row.col.f32.f16.f16.f32 "
        "{%0,%1,%2,%3}, {%4,%5,%6,%7}, {%8,%9}, {%0,%1,%2,%3};"
        : "+f"(c[0]), "+f"(c[1]), "+f"(c[2]), "+f"(c[3])
        : "r"(a[0]), "r"(a[1]), "r"(a[2]), "r"(a[3]), "r"(b[0]), "r"(b[1]));
}
__device__ __forceinline__ void ldsm4(uint32_t* r, uint32_t addr) {
    asm volatile("ldmatrix.sync.aligned.m8n8.x4.shared.b16 {%0,%1,%2,%3}, [%4];"
        : "=r"(r[0]), "=r"(r[1]), "=r"(r[2]), "=r"(r[3]) : "r"(addr));
}
// pack two floats into an fp16x2 register (lo = first arg)
__device__ __forceinline__ uint32_t packh2(float lo, float hi) {
    uint32_t d;
    asm("cvt.rn.f16x2.f32 %0, %1, %2;" : "=r"(d) : "f"(hi), "f"(lo));
    return d;
}

// ======================= scratch =======================
__device__ float  g_x[BT*EE];          // residual stream (fp32)
__device__ float  g_hf[BT*EE];         // final LN output (fp32, for logits)
__device__ __half g_h[BT*EE];          // LN output (fp16)
__device__ __half g_qkv[BT*E3];        // qkv (fp16)
__device__ __half g_att[BT*EE];        // attention out (fp16)
__device__ __half g_ff[BT*FFD];        // FF hidden (fp16)
__device__ float  g_nll[BT];
__device__ __half g_wtqkv[LL*E3*EE];   // [l][n][k] fp16
__device__ __half g_wto[LL*EE*EE];
__device__ __half g_wt1[LL*FFD*EE];
__device__ __half g_wt2[LL*EE*FFD];
__device__ float  g_woutT[VV*EE];      // [v][e] fp32

// ======================= fused embed + weight prep (single kernel, launch 0) =======================
__global__ void fused_prep(const int* __restrict__ idx, const float* __restrict__ tok,
                           const float* __restrict__ pos,
                           const float* __restrict__ Wq, const float* __restrict__ Wk,
                           const float* __restrict__ Wv, const float* __restrict__ Wo,
                           const float* __restrict__ W1, const float* __restrict__ W2,
                           const float* __restrict__ Wout) {
    const int ne = BT * EE;                         // embedding range
    const int nq = ne + LL * HH * EE * DHH;
    const int n1 = nq + LL * EE * EE;
    const int n2 = n1 + LL * EE * FFD;
    const int n3 = n2 + LL * FFD * EE;
    const int n4 = n3 + VV * EE;
    int i = blockIdx.x * blockDim.x + threadIdx.x;
    if (i < ne) {
        int e  = i % EE;
        int bt = i / EE;
        int t  = bt % TT;
        g_x[i] = tok[idx[bt] * EE + e] + pos[t * EE + e];
    } else if (i < nq) {
        int j = i - ne;
        int d = j % DHH;
        int e = (j / DHH) % EE;
        int h = (j / (DHH * EE)) % HH;
        int l = j / (DHH * EE * HH);
        int n = h * DHH + d;
        __half* dst = g_wtqkv + (size_t)l * E3 * EE;
        dst[(size_t)n * EE + e]            = __float2half_rn(Wq[j]);
        dst[(size_t)(EE + n) * EE + e]     = __float2half_rn(Wk[j]);
        dst[(size_t)(2 * EE + n) * EE + e] = __float2half_rn(Wv[j]);
    } else if (i < n1) {
        int j = i - nq;
        int k = j % EE, n = (j / EE) % EE, l = j / (EE * EE);
        g_wto[j] = __float2half_rn(Wo[(size_t)l * EE * EE + (size_t)k * EE + n]);
    } else if (i < n2) {
        int j = i - n1;
        int k = j % EE, n = (j / EE) % FFD, l = j / (EE * FFD);
        g_wt1[j] = __float2half_rn(W1[(size_t)l * EE * FFD + (size_t)k * FFD + n]);
    } else if (i < n3) {
        int j = i - n2;
        int k = j % FFD, n = (j / FFD) % EE, l = j / (FFD * EE);
        g_wt2[j] = __float2half_rn(W2[(size_t)l * FFD * EE + (size_t)k * EE + n]);
    } else if (i < n4) {
        int j = i - n3;
        int e = j % EE, v = j / EE;
        g_woutT[j] = Wout[(size_t)e * VV + v];
    }
}

// ======================= layernorm: warp per token, shuffle-only =======================
template <int HOUT>
__global__ void ln_kernel(const float* __restrict__ s, const float* __restrict__ b) {
    int tok  = (blockIdx.x * blockDim.x + threadIdx.x) >> 5;
    int lane = threadIdx.x & 31;
    const float* row = g_x + (size_t)tok * EE;

    float v[12];
    #pragma unroll
    for (int j = 0; j < 12; j++) v[j] = row[lane + 32 * j];

    float sum = 0.f;
    #pragma unroll
    for (int j = 0; j < 12; j++) sum += v[j];
    #pragma unroll
    for (int o = 16; o; o >>= 1) sum += __shfl_xor_sync(~0u, sum, o);
    float mean = sum * (1.f / EE);

    float vs = 0.f;
    #pragma unroll
    for (int j = 0; j < 12; j++) { v[j] -= mean; vs += v[j] * v[j]; }
    #pragma unroll
    for (int o = 16; o; o >>= 1) vs += __shfl_xor_sync(~0u, vs, o);
    float inv = rsqrtf(vs * (1.f / EE) + EPSV);

    if (HOUT) {
        __half* out = g_h + (size_t)tok * EE;
        #pragma unroll
        for (int j = 0; j < 12; j++) {
            int e = lane + 32 * j;
            out[e] = __float2half_rn(v[j] * inv * s[e] + b[e]);
        }
    } else {
        float* out = g_hf + (size_t)tok * EE;
        #pragma unroll
        for (int j = 0; j < 12; j++) {
            int e = lane + 32 * j;
            out[e] = v[j] * inv * s[e] + b[e];
        }
    }
}

// ======================= fp16 mma GEMM: early-issue cp.async variant =======================
#define SROWH 72
#define ABUFH (128*SROWH)     // halves per A stage
#define BBUFH (128*SROWH)     // halves per B stage
#define GSMEMB (3*(ABUFH + BBUFH) * 2)   // 110592 bytes

template <int MODE>
__global__ void __launch_bounds__(256, 2) gemm_h(
    const __half* __restrict__ A, const __half* __restrict__ Bw,
    const float* __restrict__ bias, const float* __restrict__ resid,
    void* __restrict__ Cv, int N, int K)
{
    extern __shared__ __half smh[];
    uint32_t sbase = smem_to_u32(smh);
    int tid  = threadIdx.x;
    int lane = tid & 31, warp = tid >> 5;
    int wy = warp & 3, wx = warp >> 2;        // 4 M-warps x 2 N-warps
    int g = lane >> 2, t4 = lane & 3;
    int lrow = lane & 7, seg = lane >> 3;
    int n0 = blockIdx.x * 128;
    int m0 = blockIdx.y * 128;

    uint32_t aoff0 = (uint32_t)(((wy * 32 + lrow + (seg & 1) * 8) * SROWH + (seg >> 1) * 8) * 2);
    uint32_t boff0 = (uint32_t)(((wx * 64 + lrow) * SROWH + seg * 8) * 2);

    float acc[2][8][4];
    #pragma unroll
    for (int mf = 0; mf < 2; mf++)
        #pragma unroll
        for (int nf = 0; nf < 8; nf++)
            #pragma unroll
            for (int q = 0; q < 4; q++) acc[mf][nf][q] = 0.f;

    const int nk = K >> 6;                 // BK = 64 halves

    auto load_tile = [&](int kc, int buf) {
        const __half* Ag = A  + (size_t)m0 * K + (size_t)kc * 64;
        const __half* Bg = Bw + (size_t)n0 * K + (size_t)kc * 64;
        uint32_t sA = sbase + (uint32_t)(buf * ABUFH) * 2u;
        uint32_t sB = sbase + (uint32_t)(3 * ABUFH + buf * BBUFH) * 2u;
        #pragma unroll
        for (int it = 0; it < 4; it++) {
            int i = tid + it * 256;
            int r = i >> 3, c = (i & 7) << 3;
            cp_async16(sA + (uint32_t)(r * SROWH + c) * 2u, Ag + (size_t)r * K + c);
        }
        #pragma unroll
        for (int it = 0; it < 4; it++) {
            int i = tid + it * 256;
            int r = i >> 3, c = (i & 7) << 3;
            cp_async16(sB + (uint32_t)(r * SROWH + c) * 2u, Bg + (size_t)r * K + c);
        }
    };

    load_tile(0, 0);
    CP_COMMIT();
    load_tile(1, 1);
    CP_COMMIT();

    int buf = 0;
    for (int kc = 0; kc < nk; kc++) {
        if (kc + 1 < nk) CP_WAIT1(); else CP_WAIT0();
        __syncthreads();

        // issue the kc+2 tile load NOW (before compute): buffer (kc+2)%3 was last
        // read in iteration kc-1, whose reads are ordered before this point by the
        // __syncthreads above. Gives the LDGs the whole mma block to fly.
        int nxt = kc + 2;
        if (nxt < nk) {
            int nbuf = nxt - (nxt / 3) * 3;
            load_tile(nxt, nbuf);
            CP_COMMIT();
        }

        uint32_t sAu = sbase + (uint32_t)(buf * ABUFH) * 2u;
        uint32_t sBu = sbase + (uint32_t)(3 * ABUFH + buf * BBUFH) * 2u;
        #pragma unroll
        for (int ksp = 0; ksp < 2; ksp++) {
            uint32_t kb = (uint32_t)(ksp * 64);
            uint32_t bfr[8][4];
            #pragma unroll
            for (int nf = 0; nf < 8; nf++)
                ldsm4(bfr[nf], sBu + boff0 + (uint32_t)(nf * 8 * SROWH * 2) + kb);
            #pragma unroll
            for (int mf = 0; mf < 2; mf++) {
                uint32_t af[4];
                ldsm4(af, sAu + aoff0 + (uint32_t)(mf * 16 * SROWH * 2) + kb);
                #pragma unroll
                for (int nf = 0; nf < 8; nf++)
                    mma_f16(acc[mf][nf], af, bfr[nf]);
                ldsm4(af, sAu + aoff0 + (uint32_t)(mf * 16 * SROWH * 2) + kb + 32u);
                #pragma unroll
                for (int nf = 0; nf < 8; nf++)
                    mma_f16(acc[mf][nf], af, bfr[nf] + 2);
            }
        }

        buf++; if (buf == 3) buf = 0;
    }

    // epilogue
    #pragma unroll
    for (int mf = 0; mf < 2; mf++) {
        #pragma unroll
        for (int nf = 0; nf < 8; nf++) {
            int m = m0 + wy * 32 + mf * 16 + g;
            int n = n0 + wx * 64 + nf * 8 + t4 * 2;
            #pragma unroll
            for (int rr = 0; rr < 2; rr++) {
                int mm = m + rr * 8;
                float x0 = acc[mf][nf][rr * 2];
                float x1 = acc[mf][nf][rr * 2 + 1];
                if (MODE & 1) { x0 += __ldg(bias + n); x1 += __ldg(bias + n + 1); }
                if (MODE & 2) {
                    const float* rp = resid + (size_t)mm * N + n;
                    x0 += rp[0]; x1 += rp[1];
                }
                if (MODE & 4) { x0 = fmaxf(x0, 0.f); x1 = fmaxf(x1, 0.f); }
                if (MODE & 16) {
                    __half* C = (__half*)Cv;
                    *(__half2*)(C + (size_t)mm * N + n) = __floats2half2_rn(x0, x1);
                } else {
                    float* C = (float*)Cv;
                    *(float2*)(C + (size_t)mm * N + n) = make_float2(x0, x1);
                }
            }
        }
    }
}

// ======================= fp16 flash attention (unchanged from R15) =======================
#define APADH 72
#define AQSH  (128*APADH)
#define AKTH  (64*APADH)
#define ASMEMB ((AQSH + 2*AKTH) * 2)   // 36864 bytes

__global__ void __launch_bounds__(256, 2) attn_mma() {
    extern __shared__ __half smh[];
    __half* Qs = smh;                        // [128][APADH]
    __half* Kt = smh + AQSH;                 // [64][APADH]  rows=keys, cols=d
    __half* Vt = Kt + AKTH;                  // [64][APADH]  rows=d, cols=keys
    int cta = blockIdx.x;
    int qb = cta & 1;
    int h  = (cta >> 1) % HH;
    int b  = cta / (2 * HH);
    int tid = threadIdx.x, lane = tid & 31, w = tid >> 5;
    int g = lane >> 2, t4 = lane & 3;
    int lrow = lane & 7, seg = lane >> 3;

    const __half* base = g_qkv + (size_t)b * TT * E3;

    #pragma unroll
    for (int it = 0; it < 4; it++) {
        int i = tid + it * 256;
        int r = i >> 3, c = (i & 7) << 3;
        *(uint4*)(Qs + r * APADH + c) =
            *(const uint4*)(base + (size_t)(qb * 128 + r) * E3 + h * DHH + c);
    }
    __syncthreads();

    uint32_t qaddr = smem_to_u32(Qs) + (uint32_t)(((w * 16 + lrow + (seg & 1) * 8) * APADH + (seg >> 1) * 8) * 2);
    uint32_t kaddr = smem_to_u32(Kt) + (uint32_t)((lrow * APADH + seg * 8) * 2);
    uint32_t vaddr = smem_to_u32(Vt) + (uint32_t)((lrow * APADH + seg * 8) * 2);

    float o[8][4];
    #pragma unroll
    for (int nf = 0; nf < 8; nf++) { o[nf][0] = o[nf][1] = o[nf][2] = o[nf][3] = 0.f; }
    float l0 = 0.f, l1 = 0.f;
    int qrow = qb * 128 + w * 16;
    int ktmax = qb ? 3 : 1;

    for (int kt = 0; kt <= ktmax; kt++) {
        __syncthreads();
        #pragma unroll
        for (int it = 0; it < 2; it++) {
            int i = tid + it * 256;
            int r = i >> 3, c = (i & 7) << 3;
            *(uint4*)(Kt + r * APADH + c) =
                *(const uint4*)(base + (size_t)(kt * 64 + r) * E3 + EE + h * DHH + c);
        }
        {
            int s = tid & 63, dc = (tid >> 6) << 4;
            const __half* vp = base + (size_t)(kt * 64 + s) * E3 + 2 * EE + h * DHH + dc;
            __half tmp[16];
            *(uint4*)tmp       = *(const uint4*)vp;
            *(uint4*)(tmp + 8) = *(const uint4*)(vp + 8);
            #pragma unroll
            for (int j = 0; j < 16; j++) Vt[(dc + j) * APADH + s] = tmp[j];
        }
        __syncthreads();
        if (kt * 64 > qrow + 15) continue;   // tile fully above diagonal for this warp

        uint32_t qf[4][4];
        #pragma unroll
        for (int ks = 0; ks < 4; ks++) ldsm4(qf[ks], qaddr + (uint32_t)(ks * 32));

        float s_[8][4];
        #pragma unroll
        for (int nf = 0; nf < 8; nf++) { s_[nf][0] = s_[nf][1] = s_[nf][2] = s_[nf][3] = 0.f; }
        #pragma unroll
        for (int nf = 0; nf < 8; nf++) {
            uint32_t bk[4];
            ldsm4(bk, kaddr + (uint32_t)(nf * 8 * APADH * 2));
            mma_f16(s_[nf], qf[0], bk);
            mma_f16(s_[nf], qf[1], bk + 2);
            ldsm4(bk, kaddr + (uint32_t)(nf * 8 * APADH * 2) + 64u);
            mma_f16(s_[nf], qf[2], bk);
            mma_f16(s_[nf], qf[3], bk + 2);
        }

        int cb = kt * 64 + 2 * t4;
        int q0 = qrow + g, q1 = q0 + 8;
        uint32_t p01[8], p23[8];
        #pragma unroll
        for (int nf = 0; nf < 8; nf++) {
            int c0 = cb + nf * 8, c1i = c0 + 1;
            float e0 = (c0  > q0) ? 0.f : __expf(s_[nf][0] * 0.125f);
            float e1 = (c1i > q0) ? 0.f : __expf(s_[nf][1] * 0.125f);
            float e2 = (c0  > q1) ? 0.f : __expf(s_[nf][2] * 0.125f);
            float e3 = (c1i > q1) ? 0.f : __expf(s_[nf][3] * 0.125f);
            l0 += e0 + e1;
            l1 += e2 + e3;
            p01[nf] = packh2(e0, e1);
            p23[nf] = packh2(e2, e3);
        }

        uint32_t pa[4][4];
        #pragma unroll
        for (int j = 0; j < 4; j++) {
            pa[j][0] = p01[2 * j];
            pa[j][1] = p23[2 * j];
            pa[j][2] = p01[2 * j + 1];
            pa[j][3] = p23[2 * j + 1];
        }

        #pragma unroll
        for (int nf = 0; nf < 8; nf++) {
            uint32_t bv[4];
            ldsm4(bv, vaddr + (uint32_t)(nf * 8 * APADH * 2));
            mma_f16(o[nf], pa[0], bv);
            mma_f16(o[nf], pa[1], bv + 2);
            ldsm4(bv, vaddr + (uint32_t)(nf * 8 * APADH * 2) + 64u);
            mma_f16(o[nf], pa[2], bv);
            mma_f16(o[nf], pa[3], bv + 2);
        }
    }

    l0 += __shfl_xor_sync(~0u, l0, 1); l0 += __shfl_xor_sync(~0u, l0, 2);
    l1 += __shfl_xor_sync(~0u, l1, 1); l1 += __shfl_xor_sync(~0u, l1, 2);
    float inv0 = 1.f / l0, inv1 = 1.f / l1;
    __half* op0 = g_att + (size_t)(b * TT + qrow + g) * EE + h * DHH + 2 * t4;
    __half* op1 = op0 + (size_t)8 * EE;
    #pragma unroll
    for (int nf = 0; nf < 8; nf++) {
        *(__half2*)(op0 + nf * 8) = __floats2half2_rn(o[nf][0] * inv0, o[nf][1] * inv0);
        *(__half2*)(op1 + nf * 8) = __floats2half2_rn(o[nf][2] * inv1, o[nf][3] * inv1);
    }
}

// ======================= fused logits + log_softmax + nll =======================
__global__ void logits_kernel(const float* __restrict__ bout,
                              const int* __restrict__ tgt, float* __restrict__ out) {
    __shared__ float hs[EE];
    __shared__ float sl[128];
    __shared__ float slog[VV];
    int tok = blockIdx.x;
    int tid = threadIdx.x;          // 128
    const float* row = g_hf + (size_t)tok * EE;
    hs[tid] = row[tid]; hs[tid + 128] = row[tid + 128]; hs[tid + 256] = row[tid + 256];
    __syncthreads();

    float logit = -1e30f;
    if (tid < VV) {
        float s = bout[tid];
        const float4* w4 = (const float4*)(g_woutT + (size_t)tid * EE);
        #pragma unroll 8
        for (int e = 0; e < EE / 4; e++) {
            float4 w = w4[e];
            s = fmaf(hs[4 * e], w.x, s);
            s = fmaf(hs[4 * e + 1], w.y, s);
            s = fmaf(hs[4 * e + 2], w.z, s);
            s = fmaf(hs[4 * e + 3], w.w, s);
        }
        logit = s;
        slog[tid] = s;
        out[(size_t)tok * VV + tid] = s;
    }
    sl[tid] = logit;
    __syncthreads();
    for (int o = 64; o; o >>= 1) { if (tid < o) sl[tid] = fmaxf(sl[tid], sl[tid + o]); __syncthreads(); }
    float mx = sl[0];
    __syncthreads();
    sl[tid] = (tid < VV) ? __expf(logit - mx) : 0.f;
    __syncthreads();
    for (int o = 64; o; o >>= 1) { if (tid < o) sl[tid] += sl[tid + o]; __syncthreads(); }
    if (tid == 0) {
        float logZ = mx + __logf(sl[0]);
        g_nll[tok] = logZ - slog[tgt[tok]];
    }
}

// ======================= deterministic loss reduction =======================
__global__ void loss_kernel(float* __restrict__ out) {
    __shared__ float red[256];
    float s = 0.f;
    for (int i = threadIdx.x; i < BT; i += 256) s += g_nll[i];
    red[threadIdx.x] = s;
    __syncthreads();
    for (int o = 128; o; o >>= 1) { if (threadIdx.x < o) red[threadIdx.x] += red[threadIdx.x + o]; __syncthreads(); }
    if (threadIdx.x == 0) out[(size_t)BT * VV] = red[0] * (1.f / BT);
}

// ======================= host orchestration =======================
extern "C" void kernel_launch(void* const* d_in, const int* in_sizes, int n_in,
                              void* d_out, int out_size) {
    const int*   idx  = (const int*)d_in[0];
    const int*   tgt  = (const int*)d_in[1];
    const float* tok  = (const float*)d_in[2];
    const float* pos  = (const float*)d_in[3];
    const float* Wq   = (const float*)d_in[4];
    const float* Wk   = (const float*)d_in[5];
    const float* Wv   = (const float*)d_in[6];
    const float* Wo   = (const float*)d_in[7];
    const float* bo   = (const float*)d_in[8];
    const float* l1s  = (const float*)d_in[9];
    const float* l1b  = (const float*)d_in[10];
    const float* l2s  = (const float*)d_in[11];
    const float* l2b  = (const float*)d_in[12];
    const float* W1   = (const float*)d_in[13];
    const float* b1   = (const float*)d_in[14];
    const float* W2   = (const float*)d_in[15];
    const float* b2   = (const float*)d_in[16];
    const float* lnfs = (const float*)d_in[17];
    const float* lnfb = (const float*)d_in[18];
    const float* Wout = (const float*)d_in[19];
    const float* bout = (const float*)d_in[20];
    float* out = (float*)d_out;

    cudaFuncSetAttribute(gemm_h<16>, cudaFuncAttributeMaxDynamicSharedMemorySize, GSMEMB);
    cudaFuncSetAttribute(gemm_h<3>,  cudaFuncAttributeMaxDynamicSharedMemorySize, GSMEMB);
    cudaFuncSetAttribute(gemm_h<21>, cudaFuncAttributeMaxDynamicSharedMemorySize, GSMEMB);
    cudaFuncSetAttribute(attn_mma,   cudaFuncAttributeMaxDynamicSharedMemorySize, ASMEMB);

    float *px;
    __half *ph, *pqkv, *patt, *pff, *pwtqkv, *pwto, *pwt1, *pwt2;
    cudaGetSymbolAddress((void**)&px,     g_x);
    cudaGetSymbolAddress((void**)&ph,     g_h);
    cudaGetSymbolAddress((void**)&pqkv,   g_qkv);
    cudaGetSymbolAddress((void**)&patt,   g_att);
    cudaGetSymbolAddress((void**)&pff,    g_ff);
    cudaGetSymbolAddress((void**)&pwtqkv, g_wtqkv);
    cudaGetSymbolAddress((void**)&pwto,   g_wto);
    cudaGetSymbolAddress((void**)&pwt1,   g_wt1);
    cudaGetSymbolAddress((void**)&pwt2,   g_wt2);

    {
        int total = BT*EE + LL*HH*EE*DHH + LL*EE*EE + LL*EE*FFD + LL*FFD*EE + VV*EE;
        fused_prep<<<(total + 255) / 256, 256>>>(idx, tok, pos, Wq, Wk, Wv, Wo, W1, W2, Wout);  // 0
    }

    for (int l = 0; l < LL; l++) {
        ln_kernel<1><<<BT / 8, 256>>>(l1s + l * EE, l1b + l * EE);                // 1 (l=0)
        gemm_h<16><<<dim3(E3 / 128, BT / 128), 256, GSMEMB>>>(                    // 2 (l=0)
            ph, pwtqkv + (size_t)l * E3 * EE, nullptr, nullptr, pqkv, E3, EE);
        attn_mma<<<BB * HH * 2, 256, ASMEMB>>>();                                 // 3 (l=0) <- profiled
        gemm_h<3><<<dim3(EE / 128, BT / 128), 256, GSMEMB>>>(
            patt, pwto + (size_t)l * EE * EE, bo + l * EE, px, px, EE, EE);
        ln_kernel<1><<<BT / 8, 256>>>(l2s + l * EE, l2b + l * EE);
        gemm_h<21><<<dim3(FFD / 128, BT / 128), 256, GSMEMB>>>(
            ph, pwt1 + (size_t)l * FFD * EE, b1 + l * FFD, nullptr, pff, FFD, EE);
        gemm_h<3><<<dim3(EE / 128, BT / 128), 256, GSMEMB>>>(
            pff, pwt2 + (size_t)l * EE * FFD, b2 + l * EE, px, px, EE, FFD);
    }

    ln_kernel<0><<<BT / 8, 256>>>(lnfs, lnfb);
    logits_kernel<<<BT, 128>>>(bout, tgt, out);
    loss_kernel<<<1, 256>>>(out);
}

// round 17
// speedup vs baseline: 1.0685x; 1.0685x over previous
#include <cuda_runtime.h>
#include <cuda_fp16.h>
#include <cstdint>
#include <math.h>

#define BB   128
#define TT   256
#define EE   384
#define HH   6
#define DHH  64
#define LL   6
#define VV   65
#define FFD  1536
#define BT   (BB*TT)          // 32768
#define E3   (3*EE)           // 1152
#define EPSV 1e-5f

// ======================= helpers =======================
__device__ __forceinline__ uint32_t smem_to_u32(const void* p) {
    uint32_t a;
    asm("{ .reg .u64 t; cvta.to.shared.u64 t, %1; cvt.u32.u64 %0, t; }" : "=r"(a) : "l"(p));
    return a;
}
__device__ __forceinline__ void cp_async16(uint32_t saddr, const void* gptr) {
    asm volatile("cp.async.cg.shared.global [%0], [%1], 16;" :: "r"(saddr), "l"(gptr));
}
#define CP_COMMIT() asm volatile("cp.async.commit_group;" ::: "memory")
#define CP_WAIT0()  asm volatile("cp.async.wait_group 0;" ::: "memory")
#define CP_WAIT1()  asm volatile("cp.async.wait_group 1;" ::: "memory")

// fp16 mma with fp32 accumulate
__device__ __forceinline__ void mma_f16(float* c, const uint32_t* a, const uint32_t* b) {
    asm volatile(
        "mma.sync.aligned.m16n8k16.row.col.f32.f16.f16.f32 "
        "{%0,%1,%2,%3}, {%4,%5,%6,%7}, {%8,%9}, {%0,%1,%2,%3};"
        : "+f"(c[0]), "+f"(c[1]), "+f"(c[2]), "+f"(c[3])
        : "r"(a[0]), "r"(a[1]), "r"(a[2]), "r"(a[3]), "r"(b[0]), "r"(b[1]));
}
__device__ __forceinline__ void ldsm4(uint32_t* r, uint32_t addr) {
    asm volatile("ldmatrix.sync.aligned.m8n8.x4.shared.b16 {%0,%1,%2,%3}, [%4];"
        : "=r"(r[0]), "=r"(r[1]), "=r"(r[2]), "=r"(r[3]) : "r"(addr));
}
__device__ __forceinline__ void ldsm4t(uint32_t* r, uint32_t addr) {
    asm volatile("ldmatrix.sync.aligned.m8n8.x4.trans.shared.b16 {%0,%1,%2,%3}, [%4];"
        : "=r"(r[0]), "=r"(r[1]), "=r"(r[2]), "=r"(r[3]) : "r"(addr));
}
// pack two floats into an fp16x2 register (lo = first arg)
__device__ __forceinline__ uint32_t packh2(float lo, float hi) {
    uint32_t d;
    asm("cvt.rn.f16x2.f32 %0, %1, %2;" : "=r"(d) : "f"(hi), "f"(lo));
    return d;
}

// ======================= scratch =======================
__device__ float  g_x[BT*EE];          // residual stream (fp32)
__device__ float  g_hf[BT*EE];         // final LN output (fp32, for logits)
__device__ __half g_h[BT*EE];          // LN output (fp16)
__device__ __half g_qkv[BT*E3];        // qkv (fp16)
__device__ __half g_att[BT*EE];        // attention out (fp16)
__device__ __half g_ff[BT*FFD];        // FF hidden (fp16)
__device__ float  g_nll[BT];
__device__ __half g_wtqkv[LL*E3*EE];   // [l][n][k] fp16
__device__ __half g_wto[LL*EE*EE];
__device__ __half g_wt1[LL*FFD*EE];
__device__ __half g_wt2[LL*EE*FFD];
__device__ float  g_woutT[VV*EE];      // [v][e] fp32

// ======================= fused embed + weight prep (single kernel, launch 0) =======================
__global__ void fused_prep(const int* __restrict__ idx, const float* __restrict__ tok,
                           const float* __restrict__ pos,
                           const float* __restrict__ Wq, const float* __restrict__ Wk,
                           const float* __restrict__ Wv, const float* __restrict__ Wo,
                           const float* __restrict__ W1, const float* __restrict__ W2,
                           const float* __restrict__ Wout) {
    const int ne = BT * EE;
    const int nq = ne + LL * HH * EE * DHH;
    const int n1 = nq + LL * EE * EE;
    const int n2 = n1 + LL * EE * FFD;
    const int n3 = n2 + LL * FFD * EE;
    const int n4 = n3 + VV * EE;
    int i = blockIdx.x * blockDim.x + threadIdx.x;
    if (i < ne) {
        int e  = i % EE;
        int bt = i / EE;
        int t  = bt % TT;
        g_x[i] = tok[idx[bt] * EE + e] + pos[t * EE + e];
    } else if (i < nq) {
        int j = i - ne;
        int d = j % DHH;
        int e = (j / DHH) % EE;
        int h = (j / (DHH * EE)) % HH;
        int l = j / (DHH * EE * HH);
        int n = h * DHH + d;
        __half* dst = g_wtqkv + (size_t)l * E3 * EE;
        dst[(size_t)n * EE + e]            = __float2half_rn(Wq[j]);
        dst[(size_t)(EE + n) * EE + e]     = __float2half_rn(Wk[j]);
        dst[(size_t)(2 * EE + n) * EE + e] = __float2half_rn(Wv[j]);
    } else if (i < n1) {
        int j = i - nq;
        int k = j % EE, n = (j / EE) % EE, l = j / (EE * EE);
        g_wto[j] = __float2half_rn(Wo[(size_t)l * EE * EE + (size_t)k * EE + n]);
    } else if (i < n2) {
        int j = i - n1;
        int k = j % EE, n = (j / EE) % FFD, l = j / (EE * FFD);
        g_wt1[j] = __float2half_rn(W1[(size_t)l * EE * FFD + (size_t)k * FFD + n]);
    } else if (i < n3) {
        int j = i - n2;
        int k = j % FFD, n = (j / FFD) % EE, l = j / (FFD * EE);
        g_wt2[j] = __float2half_rn(W2[(size_t)l * FFD * EE + (size_t)k * EE + n]);
    } else if (i < n4) {
        int j = i - n3;
        int e = j % EE, v = j / EE;
        g_woutT[j] = Wout[(size_t)e * VV + v];
    }
}

// ======================= layernorm: warp per token, shuffle-only =======================
template <int HOUT>
__global__ void ln_kernel(const float* __restrict__ s, const float* __restrict__ b) {
    int tok  = (blockIdx.x * blockDim.x + threadIdx.x) >> 5;
    int lane = threadIdx.x & 31;
    const float* row = g_x + (size_t)tok * EE;

    float v[12];
    #pragma unroll
    for (int j = 0; j < 12; j++) v[j] = row[lane + 32 * j];

    float sum = 0.f;
    #pragma unroll
    for (int j = 0; j < 12; j++) sum += v[j];
    #pragma unroll
    for (int o = 16; o; o >>= 1) sum += __shfl_xor_sync(~0u, sum, o);
    float mean = sum * (1.f / EE);

    float vs = 0.f;
    #pragma unroll
    for (int j = 0; j < 12; j++) { v[j] -= mean; vs += v[j] * v[j]; }
    #pragma unroll
    for (int o = 16; o; o >>= 1) vs += __shfl_xor_sync(~0u, vs, o);
    float inv = rsqrtf(vs * (1.f / EE) + EPSV);

    if (HOUT) {
        __half* out = g_h + (size_t)tok * EE;
        #pragma unroll
        for (int j = 0; j < 12; j++) {
            int e = lane + 32 * j;
            out[e] = __float2half_rn(v[j] * inv * s[e] + b[e]);
        }
    } else {
        float* out = g_hf + (size_t)tok * EE;
        #pragma unroll
        for (int j = 0; j < 12; j++) {
            int e = lane + 32 * j;
            out[e] = v[j] * inv * s[e] + b[e];
        }
    }
}

// ======================= fp16 mma GEMM (R15 late-issue form) =======================
#define SROWH 72
#define ABUFH (128*SROWH)     // halves per A stage
#define BBUFH (128*SROWH)     // halves per B stage
#define GSMEMB (3*(ABUFH + BBUFH) * 2)   // 110592 bytes

template <int MODE>
__global__ void __launch_bounds__(256, 2) gemm_h(
    const __half* __restrict__ A, const __half* __restrict__ Bw,
    const float* __restrict__ bias, const float* __restrict__ resid,
    void* __restrict__ Cv, int N, int K)
{
    extern __shared__ __half smh[];
    uint32_t sbase = smem_to_u32(smh);
    int tid  = threadIdx.x;
    int lane = tid & 31, warp = tid >> 5;
    int wy = warp & 3, wx = warp >> 2;        // 4 M-warps x 2 N-warps
    int g = lane >> 2, t4 = lane & 3;
    int lrow = lane & 7, seg = lane >> 3;
    int n0 = blockIdx.x * 128;
    int m0 = blockIdx.y * 128;

    uint32_t aoff0 = (uint32_t)(((wy * 32 + lrow + (seg & 1) * 8) * SROWH + (seg >> 1) * 8) * 2);
    uint32_t boff0 = (uint32_t)(((wx * 64 + lrow) * SROWH + seg * 8) * 2);

    float acc[2][8][4];
    #pragma unroll
    for (int mf = 0; mf < 2; mf++)
        #pragma unroll
        for (int nf = 0; nf < 8; nf++)
            #pragma unroll
            for (int q = 0; q < 4; q++) acc[mf][nf][q] = 0.f;

    const int nk = K >> 6;                 // BK = 64 halves

    auto load_tile = [&](int kc, int buf) {
        const __half* Ag = A  + (size_t)m0 * K + (size_t)kc * 64;
        const __half* Bg = Bw + (size_t)n0 * K + (size_t)kc * 64;
        uint32_t sA = sbase + (uint32_t)(buf * ABUFH) * 2u;
        uint32_t sB = sbase + (uint32_t)(3 * ABUFH + buf * BBUFH) * 2u;
        #pragma unroll
        for (int it = 0; it < 4; it++) {
            int i = tid + it * 256;
            int r = i >> 3, c = (i & 7) << 3;
            cp_async16(sA + (uint32_t)(r * SROWH + c) * 2u, Ag + (size_t)r * K + c);
        }
        #pragma unroll
        for (int it = 0; it < 4; it++) {
            int i = tid + it * 256;
            int r = i >> 3, c = (i & 7) << 3;
            cp_async16(sB + (uint32_t)(r * SROWH + c) * 2u, Bg + (size_t)r * K + c);
        }
    };

    load_tile(0, 0);
    CP_COMMIT();
    load_tile(1, 1);
    CP_COMMIT();

    int buf = 0;
    for (int kc = 0; kc < nk; kc++) {
        if (kc + 1 < nk) CP_WAIT1(); else CP_WAIT0();
        __syncthreads();

        uint32_t sAu = sbase + (uint32_t)(buf * ABUFH) * 2u;
        uint32_t sBu = sbase + (uint32_t)(3 * ABUFH + buf * BBUFH) * 2u;
        #pragma unroll
        for (int ksp = 0; ksp < 2; ksp++) {
            uint32_t kb = (uint32_t)(ksp * 64);
            uint32_t bfr[8][4];
            #pragma unroll
            for (int nf = 0; nf < 8; nf++)
                ldsm4(bfr[nf], sBu + boff0 + (uint32_t)(nf * 8 * SROWH * 2) + kb);
            #pragma unroll
            for (int mf = 0; mf < 2; mf++) {
                uint32_t af[4];
                ldsm4(af, sAu + aoff0 + (uint32_t)(mf * 16 * SROWH * 2) + kb);
                #pragma unroll
                for (int nf = 0; nf < 8; nf++)
                    mma_f16(acc[mf][nf], af, bfr[nf]);
                ldsm4(af, sAu + aoff0 + (uint32_t)(mf * 16 * SROWH * 2) + kb + 32u);
                #pragma unroll
                for (int nf = 0; nf < 8; nf++)
                    mma_f16(acc[mf][nf], af, bfr[nf] + 2);
            }
        }

        int nxt = kc + 2;
        if (nxt < nk) {
            int nbuf = nxt - (nxt / 3) * 3;
            load_tile(nxt, nbuf);
            CP_COMMIT();
        }
        buf++; if (buf == 3) buf = 0;
    }

    // epilogue
    #pragma unroll
    for (int mf = 0; mf < 2; mf++) {
        #pragma unroll
        for (int nf = 0; nf < 8; nf++) {
            int m = m0 + wy * 32 + mf * 16 + g;
            int n = n0 + wx * 64 + nf * 8 + t4 * 2;
            #pragma unroll
            for (int rr = 0; rr < 2; rr++) {
                int mm = m + rr * 8;
                float x0 = acc[mf][nf][rr * 2];
                float x1 = acc[mf][nf][rr * 2 + 1];
                if (MODE & 1) { x0 += __ldg(bias + n); x1 += __ldg(bias + n + 1); }
                if (MODE & 2) {
                    const float* rp = resid + (size_t)mm * N + n;
                    x0 += rp[0]; x1 += rp[1];
                }
                if (MODE & 4) { x0 = fmaxf(x0, 0.f); x1 = fmaxf(x1, 0.f); }
                if (MODE & 16) {
                    __half* C = (__half*)Cv;
                    *(__half2*)(C + (size_t)mm * N + n) = __floats2half2_rn(x0, x1);
                } else {
                    float* C = (float*)Cv;
                    *(float2*)(C + (size_t)mm * N + n) = make_float2(x0, x1);
                }
            }
        }
    }
}

// ======================= fp16 flash attention: trans-ldmatrix V, cp.async tiles =======================
// grid = B*H*2, 8 warps x 16 queries, key tiles of 64. P kept in registers (FA2 trick),
// no-max softmax (|s|<~3), V stored K-major and fragment-loaded via ldmatrix.trans.
#define APADH 72
#define AQSH  (128*APADH)
#define AKTH  (64*APADH)
#define ASMEMB ((AQSH + 2*AKTH) * 2)   // 36864 bytes

__global__ void __launch_bounds__(256, 2) attn_mma() {
    extern __shared__ __half smh[];
    __half* Qs = smh;                        // [128][APADH]
    __half* Kt = smh + AQSH;                 // [64][APADH]  rows=keys, cols=d
    __half* Vk = Kt + AKTH;                  // [64][APADH]  rows=keys, cols=d (K-major!)
    int cta = blockIdx.x;
    int qb = cta & 1;
    int h  = (cta >> 1) % HH;
    int b  = cta / (2 * HH);
    int tid = threadIdx.x, lane = tid & 31, w = tid >> 5;
    int g = lane >> 2, t4 = lane & 3;
    int lrow = lane & 7, seg = lane >> 3;

    const __half* base = g_qkv + (size_t)b * TT * E3;
    uint32_t ks = smem_to_u32(Kt), vs = smem_to_u32(Vk);

    // Q tile via cp.async
    #pragma unroll
    for (int it = 0; it < 4; it++) {
        int i = tid + it * 256;
        int r = i >> 3, c = (i & 7) << 3;
        cp_async16(smem_to_u32(Qs) + (uint32_t)(r * APADH + c) * 2u,
                   base + (size_t)(qb * 128 + r) * E3 + h * DHH + c);
    }
    CP_COMMIT(); CP_WAIT0();
    __syncthreads();

    uint32_t qaddr  = smem_to_u32(Qs) + (uint32_t)(((w * 16 + lrow + (seg & 1) * 8) * APADH + (seg >> 1) * 8) * 2);
    uint32_t kaddr  = ks + (uint32_t)((lrow * APADH + seg * 8) * 2);
    uint32_t vaddrt = vs + (uint32_t)(((seg * 8 + lrow) * APADH) * 2);   // trans: rows = keys

    float o[8][4];
    #pragma unroll
    for (int nf = 0; nf < 8; nf++) { o[nf][0] = o[nf][1] = o[nf][2] = o[nf][3] = 0.f; }
    float l0 = 0.f, l1 = 0.f;
    int qrow = qb * 128 + w * 16;
    int ktmax = qb ? 3 : 1;

    for (int kt = 0; kt <= ktmax; kt++) {
        __syncthreads();
        // K and V tiles via cp.async (both K-major; no scalar transpose)
        #pragma unroll
        for (int it = 0; it < 2; it++) {
            int i = tid + it * 256;
            int r = i >> 3, c = (i & 7) << 3;
            cp_async16(ks + (uint32_t)(r * APADH + c) * 2u,
                       base + (size_t)(kt * 64 + r) * E3 + EE + h * DHH + c);
        }
        #pragma unroll
        for (int it = 0; it < 2; it++) {
            int i = tid + it * 256;
            int r = i >> 3, c = (i & 7) << 3;
            cp_async16(vs + (uint32_t)(r * APADH + c) * 2u,
                       base + (size_t)(kt * 64 + r) * E3 + 2 * EE + h * DHH + c);
        }
        CP_COMMIT(); CP_WAIT0();
        __syncthreads();
        if (kt * 64 > qrow + 15) continue;

        // Q fragments (4 k-steps of 16)
        uint32_t qf[4][4];
        #pragma unroll
        for (int ksx = 0; ksx < 4; ksx++) ldsm4(qf[ksx], qaddr + (uint32_t)(ksx * 32));

        // S = Q K^T
        float s_[8][4];
        #pragma unroll
        for (int nf = 0; nf < 8; nf++) { s_[nf][0] = s_[nf][1] = s_[nf][2] = s_[nf][3] = 0.f; }
        #pragma unroll
        for (int nf = 0; nf < 8; nf++) {
            uint32_t bk[4];
            ldsm4(bk, kaddr + (uint32_t)(nf * 8 * APADH * 2));
            mma_f16(s_[nf], qf[0], bk);
            mma_f16(s_[nf], qf[1], bk + 2);
            ldsm4(bk, kaddr + (uint32_t)(nf * 8 * APADH * 2) + 64u);
            mma_f16(s_[nf], qf[2], bk);
            mma_f16(s_[nf], qf[3], bk + 2);
        }

        // scale + causal mask + exp + pack P fragments in registers
        int cb = kt * 64 + 2 * t4;
        int q0 = qrow + g, q1 = q0 + 8;
        uint32_t p01[8], p23[8];
        #pragma unroll
        for (int nf = 0; nf < 8; nf++) {
            int c0 = cb + nf * 8, c1i = c0 + 1;
            float e0 = (c0  > q0) ? 0.f : __expf(s_[nf][0] * 0.125f);
            float e1 = (c1i > q0) ? 0.f : __expf(s_[nf][1] * 0.125f);
            float e2 = (c0  > q1) ? 0.f : __expf(s_[nf][2] * 0.125f);
            float e3 = (c1i > q1) ? 0.f : __expf(s_[nf][3] * 0.125f);
            l0 += e0 + e1;
            l1 += e2 + e3;
            p01[nf] = packh2(e0, e1);
            p23[nf] = packh2(e2, e3);
        }

        uint32_t pa[4][4];
        #pragma unroll
        for (int j = 0; j < 4; j++) {
            pa[j][0] = p01[2 * j];
            pa[j][1] = p23[2 * j];
            pa[j][2] = p01[2 * j + 1];
            pa[j][3] = p23[2 * j + 1];
        }

        // O += P V : B fragments from K-major V via transposing ldmatrix
        // one ldsm4t covers keys 0..31 for d-block nf; second covers keys 32..63
        #pragma unroll
        for (int nf = 0; nf < 8; nf++) {
            uint32_t bv[4];
            ldsm4t(bv, vaddrt + (uint32_t)(nf * 16));
            mma_f16(o[nf], pa[0], bv);
            mma_f16(o[nf], pa[1], bv + 2);
            ldsm4t(bv, vaddrt + (uint32_t)(nf * 16) + (uint32_t)(32 * APADH * 2));
            mma_f16(o[nf], pa[2], bv);
            mma_f16(o[nf], pa[3], bv + 2);
        }
    }

    l0 += __shfl_xor_sync(~0u, l0, 1); l0 += __shfl_xor_sync(~0u, l0, 2);
    l1 += __shfl_xor_sync(~0u, l1, 1); l1 += __shfl_xor_sync(~0u, l1, 2);
    float inv0 = 1.f / l0, inv1 = 1.f / l1;
    __half* op0 = g_att + (size_t)(b * TT + qrow + g) * EE + h * DHH + 2 * t4;
    __half* op1 = op0 + (size_t)8 * EE;
    #pragma unroll
    for (int nf = 0; nf < 8; nf++) {
        *(__half2*)(op0 + nf * 8) = __floats2half2_rn(o[nf][0] * inv0, o[nf][1] * inv0);
        *(__half2*)(op1 + nf * 8) = __floats2half2_rn(o[nf][2] * inv1, o[nf][3] * inv1);
    }
}

// ======================= fused logits + log_softmax + nll =======================
__global__ void logits_kernel(const float* __restrict__ bout,
                              const int* __restrict__ tgt, float* __restrict__ out) {
    __shared__ float hs[EE];
    __shared__ float sl[128];
    __shared__ float slog[VV];
    int tok = blockIdx.x;
    int tid = threadIdx.x;          // 128
    const float* row = g_hf + (size_t)tok * EE;
    hs[tid] = row[tid]; hs[tid + 128] = row[tid + 128]; hs[tid + 256] = row[tid + 256];
    __syncthreads();

    float logit = -1e30f;
    if (tid < VV) {
        float s = bout[tid];
        const float4* w4 = (const float4*)(g_woutT + (size_t)tid * EE);
        #pragma unroll 8
        for (int e = 0; e < EE / 4; e++) {
            float4 w = w4[e];
            s = fmaf(hs[4 * e], w.x, s);
            s = fmaf(hs[4 * e + 1], w.y, s);
            s = fmaf(hs[4 * e + 2], w.z, s);
            s = fmaf(hs[4 * e + 3], w.w, s);
        }
        logit = s;
        slog[tid] = s;
        out[(size_t)tok * VV + tid] = s;
    }
    sl[tid] = logit;
    __syncthreads();
    for (int o = 64; o; o >>= 1) { if (tid < o) sl[tid] = fmaxf(sl[tid], sl[tid + o]); __syncthreads(); }
    float mx = sl[0];
    __syncthreads();
    sl[tid] = (tid < VV) ? __expf(logit - mx) : 0.f;
    __syncthreads();
    for (int o = 64; o; o >>= 1) { if (tid < o) sl[tid] += sl[tid + o]; __syncthreads(); }
    if (tid == 0) {
        float logZ = mx + __logf(sl[0]);
        g_nll[tok] = logZ - slog[tgt[tok]];
    }
}

// ======================= deterministic loss reduction =======================
__global__ void loss_kernel(float* __restrict__ out) {
    __shared__ float red[256];
    float s = 0.f;
    for (int i = threadIdx.x; i < BT; i += 256) s += g_nll[i];
    red[threadIdx.x] = s;
    __syncthreads();
    for (int o = 128; o; o >>= 1) { if (threadIdx.x < o) red[threadIdx.x] += red[threadIdx.x + o]; __syncthreads(); }
    if (threadIdx.x == 0) out[(size_t)BT * VV] = red[0] * (1.f / BT);
}

// ======================= host orchestration =======================
extern "C" void kernel_launch(void* const* d_in, const int* in_sizes, int n_in,
                              void* d_out, int out_size) {
    const int*   idx  = (const int*)d_in[0];
    const int*   tgt  = (const int*)d_in[1];
    const float* tok  = (const float*)d_in[2];
    const float* pos  = (const float*)d_in[3];
    const float* Wq   = (const float*)d_in[4];
    const float* Wk   = (const float*)d_in[5];
    const float* Wv   = (const float*)d_in[6];
    const float* Wo   = (const float*)d_in[7];
    const float* bo   = (const float*)d_in[8];
    const float* l1s  = (const float*)d_in[9];
    const float* l1b  = (const float*)d_in[10];
    const float* l2s  = (const float*)d_in[11];
    const float* l2b  = (const float*)d_in[12];
    const float* W1   = (const float*)d_in[13];
    const float* b1   = (const float*)d_in[14];
    const float* W2   = (const float*)d_in[15];
    const float* b2   = (const float*)d_in[16];
    const float* lnfs = (const float*)d_in[17];
    const float* lnfb = (const float*)d_in[18];
    const float* Wout = (const float*)d_in[19];
    const float* bout = (const float*)d_in[20];
    float* out = (float*)d_out;

    cudaFuncSetAttribute(gemm_h<16>, cudaFuncAttributeMaxDynamicSharedMemorySize, GSMEMB);
    cudaFuncSetAttribute(gemm_h<3>,  cudaFuncAttributeMaxDynamicSharedMemorySize, GSMEMB);
    cudaFuncSetAttribute(gemm_h<21>, cudaFuncAttributeMaxDynamicSharedMemorySize, GSMEMB);
    cudaFuncSetAttribute(attn_mma,   cudaFuncAttributeMaxDynamicSharedMemorySize, ASMEMB);

    float *px;
    __half *ph, *pqkv, *patt, *pff, *pwtqkv, *pwto, *pwt1, *pwt2;
    cudaGetSymbolAddress((void**)&px,     g_x);
    cudaGetSymbolAddress((void**)&ph,     g_h);
    cudaGetSymbolAddress((void**)&pqkv,   g_qkv);
    cudaGetSymbolAddress((void**)&patt,   g_att);
    cudaGetSymbolAddress((void**)&pff,    g_ff);
    cudaGetSymbolAddress((void**)&pwtqkv, g_wtqkv);
    cudaGetSymbolAddress((void**)&pwto,   g_wto);
    cudaGetSymbolAddress((void**)&pwt1,   g_wt1);
    cudaGetSymbolAddress((void**)&pwt2,   g_wt2);

    {
        int total = BT*EE + LL*HH*EE*DHH + LL*EE*EE + LL*EE*FFD + LL*FFD*EE + VV*EE;
        fused_prep<<<(total + 255) / 256, 256>>>(idx, tok, pos, Wq, Wk, Wv, Wo, W1, W2, Wout);  // 0
    }

    for (int l = 0; l < LL; l++) {
        ln_kernel<1><<<BT / 8, 256>>>(l1s + l * EE, l1b + l * EE);                // 1 (l=0)
        gemm_h<16><<<dim3(E3 / 128, BT / 128), 256, GSMEMB>>>(                    // 2 (l=0)
            ph, pwtqkv + (size_t)l * E3 * EE, nullptr, nullptr, pqkv, E3, EE);
        attn_mma<<<BB * HH * 2, 256, ASMEMB>>>();                                 // 3 (l=0) <- profiled
        gemm_h<3><<<dim3(EE / 128, BT / 128), 256, GSMEMB>>>(
            patt, pwto + (size_t)l * EE * EE, bo + l * EE, px, px, EE, EE);
        ln_kernel<1><<<BT / 8, 256>>>(l2s + l * EE, l2b + l * EE);
        gemm_h<21><<<dim3(FFD / 128, BT / 128), 256, GSMEMB>>>(
            ph, pwt1 + (size_t)l * FFD * EE, b1 + l * FFD, nullptr, pff, FFD, EE);
        gemm_h<3><<<dim3(EE / 128, BT / 128), 256, GSMEMB>>>(
            pff, pwt2 + (size_t)l * EE * FFD, b2 + l * EE, px, px, EE, FFD);
    }

    ln_kernel<0><<<BT / 8, 256>>>(lnfs, lnfb);
    logits_kernel<<<BT, 128>>>(bout, tgt, out);
    loss_kernel<<<1, 256>>>(out);
}